// round 8
// baseline (speedup 1.0000x reference)
#include <cuda_runtime.h>

// SpanRepLayer: pre-binned spans + fused smem-slab max kernel.
// B=8, K=2048, S=1024, H=256, W=24, WIN=3.

constexpr int Bc = 8;
constexpr int Kc = 2048;
constexpr int Sc = 1024;
constexpr int WINc = 3;

constexpr int TT = 32;          // span-start tile
constexpr int NT = Sc / TT;     // 32 tiles
constexpr int NBIN = Bc * NT;   // 256 bins
constexpr int R0 = 56;          // token rows resident (max queried row t0+54)
constexpr int C4 = 32;          // float4 per row (128-channel half)
constexpr int LISTCAP = 192;    // mean 64/bin, sd ~8 -> 16 sigma headroom

__device__ int  g_bin_cnt[NBIN];
__device__ int4 g_bin_list[NBIN * LISTCAP];   // (span, s, e, mask)

__device__ __forceinline__ float4 f4max(float4 a, float4 b) {
    return make_float4(fmaxf(a.x, b.x), fmaxf(a.y, b.y),
                       fmaxf(a.z, b.z), fmaxf(a.w, b.w));
}

// ---- reset counters (stream-ordered before binning) ----
__global__ void zero_bins() { g_bin_cnt[threadIdx.x] = 0; }

// ---- bin each span exactly once ----
__global__ __launch_bounds__(256)
void bin_spans(const int* __restrict__ ids, const int* __restrict__ masks)
{
    const int span = blockIdx.x * 256 + threadIdx.x;   // 0..16383
    const int2 se = __ldg(reinterpret_cast<const int2*>(ids) + span);
    const int m   = __ldg(masks + span);
    const int bin = (span >> 11) * NT + (se.x >> 5);
    const int p   = atomicAdd(&g_bin_cnt[bin], 1);
    if (p < LISTCAP) g_bin_list[bin * LISTCAP + p] = make_int4(span, se.x, se.y, m);
}

// ---- fused: token slab in smem, direct region maxes, one barrier ----
__global__ __launch_bounds__(512, 4)
void span_fused(const float* __restrict__ tok, float* __restrict__ out)
{
    __shared__ float4 T0[R0 * C4];                 // 28672 B

    const int tid  = threadIdx.x;
    const int half = blockIdx.x & 1;               // channel half
    const int tile = (blockIdx.x >> 1) & (NT - 1);
    const int b    = blockIdx.x >> 6;
    const int t0   = tile * TT;
    const int bin  = b * NT + tile;

    // load token slab: rows [t0, t0+56), this block's 128 channels
    const float4* g = reinterpret_cast<const float4*>(tok)
                    + (size_t)b * Sc * 64 + half * C4;
    #pragma unroll
    for (int j = 0; j < (R0 * C4 + 511) / 512; j++) {
        const int i = tid + j * 512;
        if (i < R0 * C4) {
            const int r = i >> 5, c = i & 31;
            T0[i] = __ldg(g + (size_t)min(t0 + r, Sc - 1) * 64 + c);
        }
    }
    __syncthreads();

    const int wid = tid >> 5, lane = tid & 31;
    const int n = min(__ldg(&g_bin_cnt[bin]), LISTCAP);

    #pragma unroll 2
    for (int i = wid; i < n; i += 16) {
        const int4 sp = __ldg(&g_bin_list[bin * LISTCAP + i]);
        float4* o = reinterpret_cast<float4*>(out)
                  + (size_t)sp.x * 192 + half * C4 + lane;

        if (sp.w == 0) {
            const float4 z = make_float4(0.f, 0.f, 0.f, 0.f);
            o[0] = z; o[64] = z; o[128] = z;
            continue;
        }

        const int ls = sp.y - t0;              // [0,32)
        const int le = sp.z - t0;              // <= 55
        const int w  = le - ls;

        // start: max T0[ls .. ls+min(3,w))
        float4 S = T0[ls * C4 + lane];
        if (w > 1) S = f4max(S, T0[(ls + 1) * C4 + lane]);
        if (w > 2) S = f4max(S, T0[(ls + 2) * C4 + lane]);

        // end: max T0[le-min(3,w) .. le)
        float4 E = T0[(le - 1) * C4 + lane];
        if (w > 1) E = f4max(E, T0[(le - 2) * C4 + lane]);
        if (w > 2) E = f4max(E, T0[(le - 3) * C4 + lane]);

        // inner: rows [ls+3, le-3) when w > 6, else start fallback
        float4 I = S;
        if (w > 2 * WINc) {
            I = T0[(ls + WINc) * C4 + lane];
            for (int r = ls + WINc + 1; r < le - WINc; r++)   // <=17 iters
                I = f4max(I, T0[r * C4 + lane]);
        }

        o[0] = S; o[64] = I; o[128] = E;
    }
}

extern "C" void kernel_launch(void* const* d_in, const int* in_sizes, int n_in,
                              void* d_out, int out_size)
{
    const float* tok   = (const float*)d_in[0];
    const int*   ids   = (const int*)d_in[1];
    const int*   masks = (const int*)d_in[2];
    float*       out   = (float*)d_out;

    zero_bins<<<1, NBIN>>>();
    bin_spans<<<(Bc * Kc) / 256, 256>>>(ids, masks);
    span_fused<<<NBIN * 2, 512>>>(tok, out);          // 512 blocks, one wave
}

// round 9
// speedup vs baseline: 1.2448x; 1.2448x over previous
#include <cuda_runtime.h>

// SpanRepLayer, single fused kernel: 64-row token slab in smem, direct maxes.
// B=8, K=2048, S=1024, H=256, W=24, WIN=3.

constexpr int Bc = 8;
constexpr int Kc = 2048;
constexpr int Sc = 1024;
constexpr int WINc = 3;

constexpr int TT = 64;          // span-start tile
constexpr int NT = Sc / TT;     // 16 tiles
constexpr int R0 = TT + 23;     // 87 rows (max queried row t0+86)
constexpr int C4 = 32;          // float4 per row (128-channel half)
constexpr int LISTCAP = 288;    // mean ~131 spans/tile, sd ~11

__device__ __forceinline__ float4 f4max(float4 a, float4 b) {
    return make_float4(fmaxf(a.x, b.x), fmaxf(a.y, b.y),
                       fmaxf(a.z, b.z), fmaxf(a.w, b.w));
}

__global__ __launch_bounds__(512)
void span_fused(const float* __restrict__ tok,
                const int* __restrict__ ids,
                const int* __restrict__ masks,   // bool widened to int32
                float* __restrict__ out)
{
    __shared__ float4 T0[R0 * C4];               // 44544 B
    __shared__ int4 list[LISTCAP];               // (span, ls, le, mask)
    __shared__ int nspan;

    const int tid  = threadIdx.x;
    const int half = blockIdx.x & 1;             // channel half
    const int tile = (blockIdx.x >> 1) & (NT - 1);
    const int b    = blockIdx.x >> 5;
    const int t0   = tile * TT;

    if (tid == 0) nspan = 0;
    __syncthreads();

    // ---- load token slab: rows [t0, t0+87), this block's 128 channels ----
    const float4* g = reinterpret_cast<const float4*>(tok)
                    + (size_t)b * Sc * 64 + half * C4;
    #pragma unroll
    for (int j = 0; j < (R0 * C4 + 511) / 512; j++) {
        const int i = tid + j * 512;
        if (i < R0 * C4) {
            const int r = i >> 5, c = i & 31;
            T0[i] = __ldg(g + (size_t)min(t0 + r, Sc - 1) * 64 + c);
        }
    }

    // ---- scan batch spans; compact those starting in our tile ----
    #pragma unroll
    for (int j = 0; j < Kc / 512; j++) {
        const int k = tid + j * 512;
        const int2 se = __ldg(reinterpret_cast<const int2*>(ids) + b * Kc + k);
        if ((se.x >> 6) == tile) {
            const int m = __ldg(masks + b * Kc + k);
            const int p = atomicAdd(&nspan, 1);
            if (p < LISTCAP)
                list[p] = make_int4(b * Kc + k, se.x - t0, se.y - t0, m);
        }
    }
    __syncthreads();

    // ---- per-warp span processing: pure smem + STG ----
    const int wid = tid >> 5, lane = tid & 31;
    const int n = min(nspan, LISTCAP);

    for (int i = wid; i < n; i += 16) {
        const int4 sp = list[i];
        float4* o = reinterpret_cast<float4*>(out)
                  + (size_t)sp.x * 192 + half * C4 + lane;

        if (sp.w == 0) {
            const float4 z = make_float4(0.f, 0.f, 0.f, 0.f);
            o[0] = z; o[64] = z; o[128] = z;
            continue;
        }

        const int ls = sp.y;                   // [0,64)
        const int le = sp.z;                   // <= 87
        const int w  = le - ls;

        // start: max T0[ls .. ls+min(3,w))
        float4 S = T0[ls * C4 + lane];
        if (w > 1) S = f4max(S, T0[(ls + 1) * C4 + lane]);
        if (w > 2) S = f4max(S, T0[(ls + 2) * C4 + lane]);

        // end: max T0[le-min(3,w) .. le)
        float4 E = T0[(le - 1) * C4 + lane];
        if (w > 1) E = f4max(E, T0[(le - 2) * C4 + lane]);
        if (w > 2) E = f4max(E, T0[(le - 3) * C4 + lane]);

        // inner: rows [ls+3, le-3) when w > 6, else start fallback
        float4 I = S;
        if (w > 2 * WINc) {
            const int a = ls + WINc, e3 = le - WINc;
            float4 I0 = T0[a * C4 + lane];
            float4 I1 = I0;
            int r = a + 1;
            for (; r + 1 < e3; r += 2) {       // 2-way ILP on the chain
                I0 = f4max(I0, T0[r * C4 + lane]);
                I1 = f4max(I1, T0[(r + 1) * C4 + lane]);
            }
            if (r < e3) I0 = f4max(I0, T0[r * C4 + lane]);
            I = f4max(I0, I1);
        }

        o[0] = S; o[64] = I; o[128] = E;
    }
}

extern "C" void kernel_launch(void* const* d_in, const int* in_sizes, int n_in,
                              void* d_out, int out_size)
{
    const float* tok   = (const float*)d_in[0];
    const int*   ids   = (const int*)d_in[1];
    const int*   masks = (const int*)d_in[2];
    float*       out   = (float*)d_out;

    span_fused<<<Bc * NT * 2, 512>>>(tok, ids, masks, out);   // 256 blocks
}